// round 9
// baseline (speedup 1.0000x reference)
#include <cuda_runtime.h>
#include <cstdint>

#define MG 4096
#define DD 128
#define NCHUNK 8
#define CH (MG / NCHUNK)   // 512 graphs per chunk

// device scratch — no allocation
__device__ float g_pool[MG * DD];
__device__ int   g_start[MG + 1];

__device__ __forceinline__ void f4add(float4& a, const float4& v) {
    a.x += v.x; a.y += v.y; a.z += v.z; a.w += v.w;
}

// K0: segment start table from sorted seg.
__global__ void k0_starts(const int* __restrict__ seg, int N) {
    int i = blockIdx.x * blockDim.x + threadIdx.x;
    if (i >= N) return;
    int s  = seg[i];
    int sp = (i == 0) ? -1 : seg[i - 1];
    for (int t = sp + 1; t <= s; ++t) g_start[t] = i;
    if (i == N - 1) {
        for (int t = s + 1; t <= MG; ++t) g_start[t] = N;
    }
}

// K1 chunk: segment sum for graphs [c*CH, (c+1)*CH). One block per segment.
// Rows stream in 32-row (16 KB) double-buffered cp.async.bulk stages; 256
// threads (8 row-lanes x 32 float4 chunks) reduce from smem; shared tree
// reduction writes g_pool. No atomics.
__global__ void __launch_bounds__(256) k1_chunk(const float* __restrict__ h, int chunk) {
    __shared__ float4 buf[2][32 * 32];            // 2 x 16 KB stages
    __shared__ float4 sred[8][32];
    __shared__ __align__(8) unsigned long long mbar_store[2];

    const int tid = threadIdx.x;
    const int c   = tid & 31;
    const int rl  = tid >> 5;
    const int m   = chunk * CH + blockIdx.x;

    const uint32_t mb0  = (uint32_t)__cvta_generic_to_shared(&mbar_store[0]);
    const uint32_t mb1  = (uint32_t)__cvta_generic_to_shared(&mbar_store[1]);
    const uint32_t bufa0 = (uint32_t)__cvta_generic_to_shared(&buf[0][0]);
    const uint32_t bufa1 = (uint32_t)__cvta_generic_to_shared(&buf[1][0]);

    if (tid == 0) {
        asm volatile("mbarrier.init.shared.b64 [%0], %1;" :: "r"(mb0), "r"(1u) : "memory");
        asm volatile("mbarrier.init.shared.b64 [%0], %1;" :: "r"(mb1), "r"(1u) : "memory");
    }
    __syncthreads();

    const int start = g_start[m];
    const int end   = g_start[m + 1];
    const int nrows = end - start;

    float4 a0 = make_float4(0.f, 0.f, 0.f, 0.f);
    float4 a1 = make_float4(0.f, 0.f, 0.f, 0.f);

    int ph0 = 0, ph1 = 0;

    if (nrows > 0) {
        const int nst = (nrows + 31) >> 5;

        #define ISSUE_STAGE(s)                                                         \
            do {                                                                        \
                int _b = (s) & 1;                                                       \
                int _rows = nrows - ((s) << 5); if (_rows > 32) _rows = 32;             \
                uint32_t _bytes = (uint32_t)_rows << 9;                                 \
                uint32_t _mb  = _b ? mb1 : mb0;                                         \
                uint32_t _dst = _b ? bufa1 : bufa0;                                     \
                const float* _src = h + ((size_t)(start + ((s) << 5)) << 7);            \
                asm volatile("mbarrier.arrive.expect_tx.shared.b64 _, [%0], %1;"        \
                             :: "r"(_mb), "r"(_bytes) : "memory");                      \
                asm volatile(                                                           \
                    "cp.async.bulk.shared::cluster.global.mbarrier::complete_tx::bytes "\
                    "[%0], [%1], %2, [%3];"                                             \
                    :: "r"(_dst), "l"(_src), "r"(_bytes), "r"(_mb) : "memory");         \
            } while (0)

        if (tid == 0) {
            ISSUE_STAGE(0);
            if (nst > 1) ISSUE_STAGE(1);
        }

        for (int si = 0; si < nst; ++si) {
            const int b = si & 1;
            const uint32_t mb = b ? mb1 : mb0;
            const int ph = b ? ph1 : ph0;
            uint32_t done;
            do {
                asm volatile(
                    "{\n\t.reg .pred p;\n\t"
                    "mbarrier.try_wait.parity.acquire.cta.shared::cta.b64 p, [%1], %2;\n\t"
                    "selp.b32 %0, 1, 0, p;\n\t}"
                    : "=r"(done) : "r"(mb), "r"((uint32_t)ph) : "memory");
            } while (!done);
            if (b) ph1 ^= 1; else ph0 ^= 1;

            int rows_this = nrows - (si << 5); if (rows_this > 32) rows_this = 32;
            const float4* B = buf[b];
            if (rows_this == 32) {
                float4 v0 = B[(rl)      * 32 + c];
                float4 v1 = B[(rl + 8)  * 32 + c];
                float4 v2 = B[(rl + 16) * 32 + c];
                float4 v3 = B[(rl + 24) * 32 + c];
                f4add(a0, v0); f4add(a1, v1); f4add(a0, v2); f4add(a1, v3);
            } else {
                #pragma unroll
                for (int k = 0; k < 4; ++k) {
                    int r = rl + 8 * k;
                    if (r < rows_this) f4add(a0, B[r * 32 + c]);
                }
            }
            __syncthreads();
            if (tid == 0 && si + 2 < nst) ISSUE_STAGE(si + 2);
        }
        #undef ISSUE_STAGE
    }

    f4add(a0, a1);
    sred[rl][c] = a0;
    __syncthreads();
    if (rl < 4) { f4add(a0, sred[rl + 4][c]); sred[rl][c] = a0; }
    __syncthreads();
    if (rl < 2) { f4add(a0, sred[rl + 2][c]); sred[rl][c] = a0; }
    __syncthreads();
    if (rl == 0) {
        f4add(a0, sred[1][c]);
        reinterpret_cast<float4*>(g_pool)[(size_t)m * 32 + c] = a0;
    }
}

// K2 chunk: vn_out[m] = vn_h[m] + relu((vn_h[m] + pool[m]) @ W^T + b)
__global__ void k2_chunk(const float* __restrict__ vn_h,
                         const float* __restrict__ W,
                         const float* __restrict__ b,
                         float* __restrict__ vn_out, int chunk) {
    __shared__ float xs[8][DD];
    const int m0 = chunk * CH + blockIdx.x * 8;
    const int j  = threadIdx.x;

    #pragma unroll
    for (int r = 0; r < 8; ++r) {
        int idx = (m0 + r) * DD + j;
        xs[r][j] = vn_h[idx] + g_pool[idx];
    }
    __syncthreads();

    float acc[8] = {0.f, 0.f, 0.f, 0.f, 0.f, 0.f, 0.f, 0.f};
    const float4* Wrow = reinterpret_cast<const float4*>(W + (size_t)j * DD);
    #pragma unroll 8
    for (int k4 = 0; k4 < DD / 4; ++k4) {
        float4 w = Wrow[k4];
        int k = k4 * 4;
        #pragma unroll
        for (int r = 0; r < 8; ++r) {
            acc[r] += xs[r][k + 0] * w.x;
            acc[r] += xs[r][k + 1] * w.y;
            acc[r] += xs[r][k + 2] * w.z;
            acc[r] += xs[r][k + 3] * w.w;
        }
    }

    float bj = b[j];
    #pragma unroll
    for (int r = 0; r < 8; ++r) {
        float t = acc[r] + bj;
        t = t > 0.f ? t : 0.f;
        int idx = (m0 + r) * DD + j;
        vn_out[idx] = vn_h[idx] + t;
    }
}

// K3 chunk: h_new[i] = h[i] + vn_new[seg[i]] over rows of chunk's graphs.
// Row bounds read from g_start on device; grid-stride with 4-deep batched
// float4 loads; streaming hints.
__global__ void k3_chunk(const float* __restrict__ h,
                         const int* __restrict__ seg,
                         const float* __restrict__ vn_new,
                         float* __restrict__ out, int chunk) {
    const long long lo4 = (long long)g_start[chunk * CH] * 32;
    const long long hi4 = (long long)g_start[(chunk + 1) * CH] * 32;
    const long long stride = (long long)gridDim.x * 1024;
    const float4* h4  = reinterpret_cast<const float4*>(h);
    const float4* vn4 = reinterpret_cast<const float4*>(vn_new);
    float4* out4      = reinterpret_cast<float4*>(out);

    for (long long base = lo4 + (long long)blockIdx.x * 1024 + threadIdx.x;
         base < hi4; base += stride) {
        if (base + 3 * 256 < hi4) {
            float4 a[4];
            int s[4];
            #pragma unroll
            for (int i = 0; i < 4; ++i) {
                long long idx = base + (long long)i * 256;
                a[i] = __ldcs(h4 + idx);
                s[i] = __ldg(seg + (int)(idx >> 5));
            }
            #pragma unroll
            for (int i = 0; i < 4; ++i) {
                long long idx = base + (long long)i * 256;
                float4 v = __ldg(vn4 + (long long)s[i] * 32 + (idx & 31));
                a[i].x += v.x; a[i].y += v.y; a[i].z += v.z; a[i].w += v.w;
                __stcs(out4 + idx, a[i]);
            }
        } else {
            #pragma unroll
            for (int i = 0; i < 4; ++i) {
                long long idx = base + (long long)i * 256;
                if (idx >= hi4) break;
                int s = __ldg(seg + (int)(idx >> 5));
                float4 a = __ldcs(h4 + idx);
                float4 v = __ldg(vn4 + (long long)s * 32 + (idx & 31));
                a.x += v.x; a.y += v.y; a.z += v.z; a.w += v.w;
                __stcs(out4 + idx, a);
            }
        }
    }
}

extern "C" void kernel_launch(void* const* d_in, const int* in_sizes, int n_in,
                              void* d_out, int out_size) {
    const float* h    = (const float*)d_in[0];      // [N, 128]
    const float* vn_h = (const float*)d_in[1];      // [4096, 128]
    const int*   seg  = (const int*)d_in[2];        // [N] sorted int32
    const float* W    = (const float*)d_in[3];      // [128, 128]
    const float* b    = (const float*)d_in[4];      // [128]

    const int N = in_sizes[0] / DD;                   // 1,000,000
    float* out_h  = (float*)d_out;                    // h_new [N,128]
    float* out_vn = (float*)d_out + (size_t)N * DD;   // vn_h_new [4096,128]

    // Auxiliary stream + events for pipelined fork/join (host objects only;
    // cannot be destroyed while the parent stream's capture is active, so
    // they are intentionally not destroyed — kernel_launch is called only
    // for correctness + capture).
    cudaStream_t s1;
    cudaStreamCreate(&s1);
    cudaEvent_t ev[NCHUNK], evj;
    for (int c = 0; c < NCHUNK; ++c)
        cudaEventCreateWithFlags(&ev[c], cudaEventDisableTiming);
    cudaEventCreateWithFlags(&evj, cudaEventDisableTiming);

    // K0 on main (legacy) stream
    k0_starts<<<(N + 255) / 256, 256>>>(seg, N);

    for (int c = 0; c < NCHUNK; ++c) {
        // producer side: segment sums + vn update for chunk c (main stream)
        k1_chunk<<<CH, 256>>>(h, c);
        k2_chunk<<<CH / 8, DD>>>(vn_h, W, b, out_vn, c);
        cudaEventRecord(ev[c], 0);
        // consumer side: broadcast-add for chunk c (aux stream, overlaps
        // with k1_chunk(c+1) reads on the main stream)
        cudaStreamWaitEvent(s1, ev[c], 0);
        k3_chunk<<<1024, 256, 0, s1>>>(h, seg, out_vn, out_h, c);
    }

    // join: main stream (and thus the harness) waits for all K3 chunks
    cudaEventRecord(evj, s1);
    cudaStreamWaitEvent(0, evj, 0);
}

// round 10
// speedup vs baseline: 1.0631x; 1.0631x over previous
#include <cuda_runtime.h>
#include <cstdint>

#define MG 4096
#define DD 128
#define K1_BLOCKS 912

// device scratch — no allocation
__device__ int g_start[MG + 1];
__device__ unsigned int g_counter;

__device__ __forceinline__ void f4add(float4& a, const float4& v) {
    a.x += v.x; a.y += v.y; a.z += v.z; a.w += v.w;
}

// K0: segment start table from sorted seg + reset work counter.
__global__ void k0_starts(const int* __restrict__ seg, int N) {
    int i = blockIdx.x * blockDim.x + threadIdx.x;
    if (i == 0) g_counter = 0;
    if (i >= N) return;
    int s  = seg[i];
    int sp = (i == 0) ? -1 : seg[i - 1];
    for (int t = sp + 1; t <= s; ++t) g_start[t] = i;
    if (i == N - 1) {
        for (int t = s + 1; t <= MG; ++t) g_start[t] = N;
    }
}

// K1: fused segment-sum + virtual-node update.
// 912 persistent blocks steal segments from a global counter. Per segment:
// rows stream in 32-row (16 KB) double-buffered cp.async.bulk stages; 256
// threads (8 row-lanes x 32 float4 chunks) reduce from smem (tree reduction),
// then the SAME block runs the 128x128 GEMV epilogue:
//   vn_out[m] = vn_h[m] + relu((vn_h[m] + pool) @ W^T + b)
// No g_pool, no separate K2 kernel, no atomics on data.
__global__ void __launch_bounds__(256) k1_fused(const float* __restrict__ h,
                                                const float* __restrict__ vn_h,
                                                const float* __restrict__ W,
                                                const float* __restrict__ bias,
                                                float* __restrict__ vn_out) {
    __shared__ float4 buf[2][32 * 32];            // 2 x 16 KB stages
    __shared__ float4 sred[8][32];                // reduction scratch
    __shared__ float  xv[DD];                     // x = vn_h[m] + pool
    __shared__ float  part[DD];                   // GEMV partials
    __shared__ int sm;                            // stolen segment id
    __shared__ __align__(8) unsigned long long mbar_store[2];

    const int tid = threadIdx.x;
    const int c   = tid & 31;
    const int rl  = tid >> 5;

    const uint32_t mb0  = (uint32_t)__cvta_generic_to_shared(&mbar_store[0]);
    const uint32_t mb1  = (uint32_t)__cvta_generic_to_shared(&mbar_store[1]);
    const uint32_t bufa0 = (uint32_t)__cvta_generic_to_shared(&buf[0][0]);
    const uint32_t bufa1 = (uint32_t)__cvta_generic_to_shared(&buf[1][0]);

    if (tid == 0) {
        asm volatile("mbarrier.init.shared.b64 [%0], %1;" :: "r"(mb0), "r"(1u) : "memory");
        asm volatile("mbarrier.init.shared.b64 [%0], %1;" :: "r"(mb1), "r"(1u) : "memory");
    }
    __syncthreads();

    int ph0 = 0, ph1 = 0;   // per-slot phase parity

    for (;;) {
        if (tid == 0) sm = (int)atomicAdd(&g_counter, 1u);
        __syncthreads();
        const int m = sm;
        if (m >= MG) break;

        const int start = g_start[m];
        const int end   = g_start[m + 1];
        const int nrows = end - start;

        float4 a0 = make_float4(0.f, 0.f, 0.f, 0.f);
        float4 a1 = make_float4(0.f, 0.f, 0.f, 0.f);

        if (nrows > 0) {
            const int nst = (nrows + 31) >> 5;

            #define ISSUE_STAGE(s)                                                         \
                do {                                                                        \
                    int _b = (s) & 1;                                                       \
                    int _rows = nrows - ((s) << 5); if (_rows > 32) _rows = 32;             \
                    uint32_t _bytes = (uint32_t)_rows << 9;                                 \
                    uint32_t _mb  = _b ? mb1 : mb0;                                         \
                    uint32_t _dst = _b ? bufa1 : bufa0;                                     \
                    const float* _src = h + ((size_t)(start + ((s) << 5)) << 7);            \
                    asm volatile("mbarrier.arrive.expect_tx.shared.b64 _, [%0], %1;"        \
                                 :: "r"(_mb), "r"(_bytes) : "memory");                      \
                    asm volatile(                                                           \
                        "cp.async.bulk.shared::cluster.global.mbarrier::complete_tx::bytes "\
                        "[%0], [%1], %2, [%3];"                                             \
                        :: "r"(_dst), "l"(_src), "r"(_bytes), "r"(_mb) : "memory");         \
                } while (0)

            if (tid == 0) {
                ISSUE_STAGE(0);
                if (nst > 1) ISSUE_STAGE(1);
            }

            for (int si = 0; si < nst; ++si) {
                const int b = si & 1;
                const uint32_t mb = b ? mb1 : mb0;
                const int ph = b ? ph1 : ph0;
                uint32_t done;
                do {
                    asm volatile(
                        "{\n\t.reg .pred p;\n\t"
                        "mbarrier.try_wait.parity.acquire.cta.shared::cta.b64 p, [%1], %2;\n\t"
                        "selp.b32 %0, 1, 0, p;\n\t}"
                        : "=r"(done) : "r"(mb), "r"((uint32_t)ph) : "memory");
                } while (!done);
                if (b) ph1 ^= 1; else ph0 ^= 1;

                int rows_this = nrows - (si << 5); if (rows_this > 32) rows_this = 32;
                const float4* B = buf[b];
                if (rows_this == 32) {
                    float4 v0 = B[(rl)      * 32 + c];
                    float4 v1 = B[(rl + 8)  * 32 + c];
                    float4 v2 = B[(rl + 16) * 32 + c];
                    float4 v3 = B[(rl + 24) * 32 + c];
                    f4add(a0, v0); f4add(a1, v1); f4add(a0, v2); f4add(a1, v3);
                } else {
                    #pragma unroll
                    for (int k = 0; k < 4; ++k) {
                        int r = rl + 8 * k;
                        if (r < rows_this) f4add(a0, B[r * 32 + c]);
                    }
                }
                __syncthreads();   // everyone done reading buf[b]
                if (tid == 0 && si + 2 < nst) ISSUE_STAGE(si + 2);
            }
            #undef ISSUE_STAGE
        }

        // tree-reduce 8 row-lanes -> pool[m] (float4 per c at rl==0)
        f4add(a0, a1);
        sred[rl][c] = a0;
        __syncthreads();
        if (rl < 4) { f4add(a0, sred[rl + 4][c]); sred[rl][c] = a0; }
        __syncthreads();
        if (rl < 2) { f4add(a0, sred[rl + 2][c]); sred[rl][c] = a0; }
        __syncthreads();
        if (rl == 0) {
            f4add(a0, sred[1][c]);
            // x = vn_h[m] + pool
            float4 vh = *reinterpret_cast<const float4*>(vn_h + (size_t)m * DD + 4 * c);
            f4add(a0, vh);
            *reinterpret_cast<float4*>(&xv[4 * c]) = a0;
        }
        __syncthreads();

        // GEMV epilogue: 2 threads per output row j (halves of the K dim)
        {
            const int j    = tid >> 1;
            const int half = tid & 1;
            const float4* Wr = reinterpret_cast<const float4*>(W + (size_t)j * DD + half * 64);
            const float* xp0 = &xv[half * 64];
            float s = 0.f;
            #pragma unroll
            for (int k4 = 0; k4 < 16; ++k4) {
                float4 w = Wr[k4];
                const float* xp = xp0 + k4 * 4;
                s += xp[0] * w.x + xp[1] * w.y + xp[2] * w.z + xp[3] * w.w;
            }
            if (half) part[j] = s;
            __syncthreads();
            if (!half) {
                float t = s + part[j] + bias[j];
                t = t > 0.f ? t : 0.f;
                vn_out[(size_t)m * DD + j] = vn_h[(size_t)m * DD + j] + t;
            }
        }
        __syncthreads();   // shared reuse before next stolen segment
    }
}

// K3: h_new[i] = h[i] + vn_new[seg[i]]
// 4 float4 chunks per thread, loads front-batched; streaming hints.
__global__ void k3_broadcast_add(const float* __restrict__ h,
                                 const int* __restrict__ seg,
                                 const float* __restrict__ vn_new,
                                 float* __restrict__ out, int N) {
    const long long total = (long long)N * (DD / 4);
    const long long base = (long long)blockIdx.x * 1024 + threadIdx.x;
    const float4* h4  = reinterpret_cast<const float4*>(h);
    const float4* vn4 = reinterpret_cast<const float4*>(vn_new);
    float4* out4      = reinterpret_cast<float4*>(out);

    if (base + 3 * 256 < total) {
        float4 a[4];
        int s[4];
        #pragma unroll
        for (int i = 0; i < 4; ++i) {
            long long idx = base + (long long)i * 256;
            a[i] = __ldcs(h4 + idx);
            s[i] = __ldg(seg + (int)(idx >> 5));
        }
        #pragma unroll
        for (int i = 0; i < 4; ++i) {
            long long idx = base + (long long)i * 256;
            float4 v = __ldg(vn4 + (long long)s[i] * 32 + (idx & 31));
            a[i].x += v.x; a[i].y += v.y; a[i].z += v.z; a[i].w += v.w;
            __stcs(out4 + idx, a[i]);
        }
    } else {
        #pragma unroll
        for (int i = 0; i < 4; ++i) {
            long long idx = base + (long long)i * 256;
            if (idx >= total) break;
            int s = __ldg(seg + (int)(idx >> 5));
            float4 a = __ldcs(h4 + idx);
            float4 v = __ldg(vn4 + (long long)s * 32 + (idx & 31));
            a.x += v.x; a.y += v.y; a.z += v.z; a.w += v.w;
            __stcs(out4 + idx, a);
        }
    }
}

extern "C" void kernel_launch(void* const* d_in, const int* in_sizes, int n_in,
                              void* d_out, int out_size) {
    const float* h    = (const float*)d_in[0];      // [N, 128]
    const float* vn_h = (const float*)d_in[1];      // [4096, 128]
    const int*   seg  = (const int*)d_in[2];        // [N] sorted int32
    const float* W    = (const float*)d_in[3];      // [128, 128]
    const float* b    = (const float*)d_in[4];      // [128]

    const int N = in_sizes[0] / DD;                   // 1,000,000
    float* out_h  = (float*)d_out;                    // h_new [N,128]
    float* out_vn = (float*)d_out + (size_t)N * DD;   // vn_h_new [4096,128]

    // K0: segment start table + counter reset
    k0_starts<<<(N + 255) / 256, 256>>>(seg, N);

    // K1: fused work-stealing segment-sum + vn update (912 persistent blocks)
    k1_fused<<<K1_BLOCKS, 256>>>(h, vn_h, W, b, out_vn);

    // K3: broadcast-add back to nodes
    long long total4 = (long long)N * (DD / 4);
    int blocks = (int)((total4 + 1023) / 1024);
    k3_broadcast_add<<<blocks, 256>>>(h, seg, out_vn, out_h, N);
}

// round 11
// speedup vs baseline: 1.1320x; 1.0649x over previous
#include <cuda_runtime.h>
#include <cstdint>

#define MG 4096
#define DD 128
#define K1_BLOCKS 912

// device scratch — no allocation
__device__ float g_pool[MG * DD];
__device__ int   g_start[MG + 1];
__device__ unsigned int g_counter;

__device__ __forceinline__ void f4add(float4& a, const float4& v) {
    a.x += v.x; a.y += v.y; a.z += v.z; a.w += v.w;
}

// K0: segment start table from sorted seg (vectorized: int4 per thread).
// Boundary writes only where seg changes (4096 total). Also resets the
// work-stealing counter.
__global__ void k0_starts(const int* __restrict__ seg, int N) {
    int t = blockIdx.x * blockDim.x + threadIdx.x;
    if (t == 0) g_counter = 0;
    int base = t * 4;
    if (base >= N) return;

    int4 v = *reinterpret_cast<const int4*>(seg + base);   // N % 4 == 0
    int prev = (base == 0) ? -1 : __ldg(seg + base - 1);

    int e[4] = {v.x, v.y, v.z, v.w};
    #pragma unroll
    for (int k = 0; k < 4; ++k) {
        int cur = e[k];
        if (cur != prev) {
            for (int s = prev + 1; s <= cur; ++s) g_start[s] = base + k;
        }
        prev = cur;
    }
    if (base + 4 >= N) {
        for (int s = prev + 1; s <= MG; ++s) g_start[s] = N;
    }
}

// K1: segment sum via TMA bulk pipeline + segment work-stealing.
// 912 persistent blocks; each grabs segments from a global counter (perfect
// load balance, single wave). Per segment: rows stream in 32-row (16 KB)
// double-buffered cp.async.bulk stages; 256 threads (8 row-lanes x 32 float4
// chunks) reduce from smem; shared tree reduction writes g_pool. No atomics
// on data.
__global__ void __launch_bounds__(256) k1_seg_sum_tma(const float* __restrict__ h) {
    __shared__ float4 buf[2][32 * 32];            // 2 x 16 KB stages
    __shared__ float4 sred[8][32];                // 4 KB reduction scratch
    __shared__ int sm;                            // stolen segment id
    __shared__ __align__(8) unsigned long long mbar_store[2];

    const int tid = threadIdx.x;
    const int c   = tid & 31;
    const int rl  = tid >> 5;

    const uint32_t mb0  = (uint32_t)__cvta_generic_to_shared(&mbar_store[0]);
    const uint32_t mb1  = (uint32_t)__cvta_generic_to_shared(&mbar_store[1]);
    const uint32_t bufa0 = (uint32_t)__cvta_generic_to_shared(&buf[0][0]);
    const uint32_t bufa1 = (uint32_t)__cvta_generic_to_shared(&buf[1][0]);

    if (tid == 0) {
        asm volatile("mbarrier.init.shared.b64 [%0], %1;" :: "r"(mb0), "r"(1u) : "memory");
        asm volatile("mbarrier.init.shared.b64 [%0], %1;" :: "r"(mb1), "r"(1u) : "memory");
    }
    __syncthreads();

    int ph0 = 0, ph1 = 0;   // per-slot phase parity

    for (;;) {
        if (tid == 0) sm = (int)atomicAdd(&g_counter, 1u);
        __syncthreads();
        const int m = sm;
        if (m >= MG) break;

        const int start = g_start[m];
        const int end   = g_start[m + 1];
        const int nrows = end - start;

        float4 a0 = make_float4(0.f, 0.f, 0.f, 0.f);
        float4 a1 = make_float4(0.f, 0.f, 0.f, 0.f);

        if (nrows > 0) {
            const int nst = (nrows + 31) >> 5;

            #define ISSUE_STAGE(s)                                                         \
                do {                                                                        \
                    int _b = (s) & 1;                                                       \
                    int _rows = nrows - ((s) << 5); if (_rows > 32) _rows = 32;             \
                    uint32_t _bytes = (uint32_t)_rows << 9;                                 \
                    uint32_t _mb  = _b ? mb1 : mb0;                                         \
                    uint32_t _dst = _b ? bufa1 : bufa0;                                     \
                    const float* _src = h + ((size_t)(start + ((s) << 5)) << 7);            \
                    asm volatile("mbarrier.arrive.expect_tx.shared.b64 _, [%0], %1;"        \
                                 :: "r"(_mb), "r"(_bytes) : "memory");                      \
                    asm volatile(                                                           \
                        "cp.async.bulk.shared::cluster.global.mbarrier::complete_tx::bytes "\
                        "[%0], [%1], %2, [%3];"                                             \
                        :: "r"(_dst), "l"(_src), "r"(_bytes), "r"(_mb) : "memory");         \
                } while (0)

            if (tid == 0) {
                ISSUE_STAGE(0);
                if (nst > 1) ISSUE_STAGE(1);
            }

            for (int si = 0; si < nst; ++si) {
                const int b = si & 1;
                const uint32_t mb = b ? mb1 : mb0;
                const int ph = b ? ph1 : ph0;
                uint32_t done;
                do {
                    asm volatile(
                        "{\n\t.reg .pred p;\n\t"
                        "mbarrier.try_wait.parity.acquire.cta.shared::cta.b64 p, [%1], %2;\n\t"
                        "selp.b32 %0, 1, 0, p;\n\t}"
                        : "=r"(done) : "r"(mb), "r"((uint32_t)ph) : "memory");
                } while (!done);
                if (b) ph1 ^= 1; else ph0 ^= 1;

                int rows_this = nrows - (si << 5); if (rows_this > 32) rows_this = 32;
                const float4* B = buf[b];
                if (rows_this == 32) {
                    float4 v0 = B[(rl)      * 32 + c];
                    float4 v1 = B[(rl + 8)  * 32 + c];
                    float4 v2 = B[(rl + 16) * 32 + c];
                    float4 v3 = B[(rl + 24) * 32 + c];
                    f4add(a0, v0); f4add(a1, v1); f4add(a0, v2); f4add(a1, v3);
                } else {
                    #pragma unroll
                    for (int k = 0; k < 4; ++k) {
                        int r = rl + 8 * k;
                        if (r < rows_this) f4add(a0, B[r * 32 + c]);
                    }
                }
                __syncthreads();   // everyone done reading buf[b]
                if (tid == 0 && si + 2 < nst) ISSUE_STAGE(si + 2);
            }
            #undef ISSUE_STAGE
        }

        f4add(a0, a1);
        sred[rl][c] = a0;
        __syncthreads();
        if (rl < 4) { f4add(a0, sred[rl + 4][c]); sred[rl][c] = a0; }
        __syncthreads();
        if (rl < 2) { f4add(a0, sred[rl + 2][c]); sred[rl][c] = a0; }
        __syncthreads();
        if (rl == 0) {
            f4add(a0, sred[1][c]);
            reinterpret_cast<float4*>(g_pool)[(size_t)m * 32 + c] = a0;
        }
        __syncthreads();
    }
}

// K2: vn_out[m] = vn_h[m] + relu((vn_h[m] + pool[m]) @ W^T + b)
__global__ void k2_vn_update(const float* __restrict__ vn_h,
                             const float* __restrict__ W,
                             const float* __restrict__ b,
                             float* __restrict__ vn_out) {
    __shared__ float xs[8][DD];
    const int m0 = blockIdx.x * 8;
    const int j  = threadIdx.x;

    #pragma unroll
    for (int r = 0; r < 8; ++r) {
        int idx = (m0 + r) * DD + j;
        xs[r][j] = vn_h[idx] + g_pool[idx];
    }
    __syncthreads();

    float acc[8] = {0.f, 0.f, 0.f, 0.f, 0.f, 0.f, 0.f, 0.f};
    const float4* Wrow = reinterpret_cast<const float4*>(W + (size_t)j * DD);
    #pragma unroll 8
    for (int k4 = 0; k4 < DD / 4; ++k4) {
        float4 w = Wrow[k4];
        int k = k4 * 4;
        #pragma unroll
        for (int r = 0; r < 8; ++r) {
            acc[r] += xs[r][k + 0] * w.x;
            acc[r] += xs[r][k + 1] * w.y;
            acc[r] += xs[r][k + 2] * w.z;
            acc[r] += xs[r][k + 3] * w.w;
        }
    }

    float bj = b[j];
    #pragma unroll
    for (int r = 0; r < 8; ++r) {
        float t = acc[r] + bj;
        t = t > 0.f ? t : 0.f;
        int idx = (m0 + r) * DD + j;
        vn_out[idx] = vn_h[idx] + t;
    }
}

// K3: h_new[i] = h[i] + vn_new[seg[i]]
// 4 float4 chunks per thread, loads front-batched; streaming hints.
__global__ void k3_broadcast_add(const float* __restrict__ h,
                                 const int* __restrict__ seg,
                                 const float* __restrict__ vn_new,
                                 float* __restrict__ out, int N) {
    const long long total = (long long)N * (DD / 4);
    const long long base = (long long)blockIdx.x * 1024 + threadIdx.x;
    const float4* h4  = reinterpret_cast<const float4*>(h);
    const float4* vn4 = reinterpret_cast<const float4*>(vn_new);
    float4* out4      = reinterpret_cast<float4*>(out);

    if (base + 3 * 256 < total) {
        float4 a[4];
        int s[4];
        #pragma unroll
        for (int i = 0; i < 4; ++i) {
            long long idx = base + (long long)i * 256;
            a[i] = __ldcs(h4 + idx);
            s[i] = __ldg(seg + (int)(idx >> 5));
        }
        #pragma unroll
        for (int i = 0; i < 4; ++i) {
            long long idx = base + (long long)i * 256;
            float4 v = __ldg(vn4 + (long long)s[i] * 32 + (idx & 31));
            a[i].x += v.x; a[i].y += v.y; a[i].z += v.z; a[i].w += v.w;
            __stcs(out4 + idx, a[i]);
        }
    } else {
        #pragma unroll
        for (int i = 0; i < 4; ++i) {
            long long idx = base + (long long)i * 256;
            if (idx >= total) break;
            int s = __ldg(seg + (int)(idx >> 5));
            float4 a = __ldcs(h4 + idx);
            float4 v = __ldg(vn4 + (long long)s * 32 + (idx & 31));
            a.x += v.x; a.y += v.y; a.z += v.z; a.w += v.w;
            __stcs(out4 + idx, a);
        }
    }
}

extern "C" void kernel_launch(void* const* d_in, const int* in_sizes, int n_in,
                              void* d_out, int out_size) {
    const float* h    = (const float*)d_in[0];      // [N, 128]
    const float* vn_h = (const float*)d_in[1];      // [4096, 128]
    const int*   seg  = (const int*)d_in[2];        // [N] sorted int32
    const float* W    = (const float*)d_in[3];      // [128, 128]
    const float* b    = (const float*)d_in[4];      // [128]

    const int N = in_sizes[0] / DD;                   // 1,000,000
    float* out_h  = (float*)d_out;                    // h_new [N,128]
    float* out_vn = (float*)d_out + (size_t)N * DD;   // vn_h_new [4096,128]

    // K0: segment start table + counter reset (int4-vectorized)
    int k0_threads = (N + 3) / 4;
    k0_starts<<<(k0_threads + 255) / 256, 256>>>(seg, N);

    // K1: work-stealing TMA segment sum (912 persistent blocks, 6/SM)
    k1_seg_sum_tma<<<K1_BLOCKS, 256>>>(h);

    // K2: virtual-node update
    k2_vn_update<<<MG / 8, DD>>>(vn_h, W, b, out_vn);

    // K3: broadcast-add back to nodes
    long long total4 = (long long)N * (DD / 4);
    int blocks = (int)((total4 + 1023) / 1024);
    k3_broadcast_add<<<blocks, 256>>>(h, seg, out_vn, out_h, N);
}

// round 12
// speedup vs baseline: 1.2048x; 1.0643x over previous
#include <cuda_runtime.h>
#include <cstdint>

#define MG 4096
#define DD 128
#define K1_BLOCKS 760   // 5 blocks/SM x 152 SMs (smem-limited)

// device scratch — no allocation
__device__ int g_start[MG + 1];
__device__ unsigned int g_counter;

__device__ __forceinline__ void f4add(float4& a, const float4& v) {
    a.x += v.x; a.y += v.y; a.z += v.z; a.w += v.w;
}

// K0: segment start table from sorted seg (int4 per thread) + counter reset.
__global__ void k0_starts(const int* __restrict__ seg, int N) {
    int t = blockIdx.x * blockDim.x + threadIdx.x;
    if (t == 0) g_counter = 0;
    int base = t * 4;
    if (base >= N) return;

    int4 v = *reinterpret_cast<const int4*>(seg + base);   // N % 4 == 0
    int prev = (base == 0) ? -1 : __ldg(seg + base - 1);

    int e[4] = {v.x, v.y, v.z, v.w};
    #pragma unroll
    for (int k = 0; k < 4; ++k) {
        int cur = e[k];
        if (cur != prev) {
            for (int s = prev + 1; s <= cur; ++s) g_start[s] = base + k;
        }
        prev = cur;
    }
    if (base + 4 >= N) {
        for (int s = prev + 1; s <= MG; ++s) g_start[s] = N;
    }
}

// Fused kernel: per stolen segment m —
//   (a) TMA double-buffered sum of h rows -> pool
//   (b) GEMV epilogue: y = vn_h[m] + relu((vn_h[m]+pool) @ W^T + b) -> vn_out, smem
//   (c) broadcast: out_h[row] = h[row] (L2-resident re-read) + y
// Next segment is stolen and its first TMA stages issued BEFORE phase (c),
// keeping the load pipe busy through the epilogue+broadcast.
__global__ void __launch_bounds__(256) k_fused(const float* __restrict__ h,
                                               const float* __restrict__ vn_h,
                                               const float* __restrict__ W,
                                               const float* __restrict__ bias,
                                               float* __restrict__ vn_out,
                                               float* __restrict__ out_h) {
    __shared__ float4 buf[2][32 * 32];            // 2 x 16 KB TMA stages
    __shared__ float4 sred[8][32];                // tree-reduction scratch
    __shared__ __align__(16) float xv[DD];        // x = vn_h[m] + pool
    __shared__ __align__(16) float part[DD];      // GEMV partials
    __shared__ __align__(16) float yv[DD];        // y = vn_new[m]
    __shared__ int sm_next;
    __shared__ __align__(8) unsigned long long mbar_store[2];

    const int tid = threadIdx.x;
    const int c   = tid & 31;    // float4 chunk in row
    const int rl  = tid >> 5;    // row lane

    const uint32_t mb[2] = {
        (uint32_t)__cvta_generic_to_shared(&mbar_store[0]),
        (uint32_t)__cvta_generic_to_shared(&mbar_store[1]) };
    const uint32_t bufa[2] = {
        (uint32_t)__cvta_generic_to_shared(&buf[0][0]),
        (uint32_t)__cvta_generic_to_shared(&buf[1][0]) };

    if (tid == 0) {
        asm volatile("mbarrier.init.shared.b64 [%0], %1;" :: "r"(mb[0]), "r"(1u) : "memory");
        asm volatile("mbarrier.init.shared.b64 [%0], %1;" :: "r"(mb[1]), "r"(1u) : "memory");
    }
    __syncthreads();

    int ph0 = 0, ph1 = 0;

    const float4* h4  = reinterpret_cast<const float4*>(h);
    float4* out4      = reinterpret_cast<float4*>(out_h);

    #define ISSUE_STAGE(sstart, snrows, s)                                             \
        do {                                                                            \
            int _b = (s) & 1;                                                           \
            int _rows = (snrows) - ((s) << 5); if (_rows > 32) _rows = 32;              \
            uint32_t _bytes = (uint32_t)_rows << 9;                                     \
            const float* _src = h + ((size_t)((sstart) + ((s) << 5)) << 7);             \
            asm volatile("mbarrier.arrive.expect_tx.shared.b64 _, [%0], %1;"            \
                         :: "r"(mb[_b]), "r"(_bytes) : "memory");                       \
            asm volatile(                                                               \
                "cp.async.bulk.shared::cluster.global.mbarrier::complete_tx::bytes "    \
                "[%0], [%1], %2, [%3];"                                                 \
                :: "r"(bufa[_b]), "l"(_src), "r"(_bytes), "r"(mb[_b]) : "memory");      \
        } while (0)

    // initial steal + prefetch
    if (tid == 0) sm_next = (int)atomicAdd(&g_counter, 1u);
    __syncthreads();
    int m = sm_next;
    int start = 0, end = 0, nrows = 0, nst = 0;
    if (m < MG) {
        start = g_start[m]; end = g_start[m + 1];
        nrows = end - start; nst = (nrows + 31) >> 5;
        if (tid == 0 && nst > 0) {
            ISSUE_STAGE(start, nrows, 0);
            if (nst > 1) ISSUE_STAGE(start, nrows, 1);
        }
    }

    while (m < MG) {
        // ---- (a) sum phase ----
        float4 a0 = make_float4(0.f, 0.f, 0.f, 0.f);
        float4 a1 = make_float4(0.f, 0.f, 0.f, 0.f);

        for (int si = 0; si < nst; ++si) {
            const int b = si & 1;
            const int ph = b ? ph1 : ph0;
            uint32_t done;
            do {
                asm volatile(
                    "{\n\t.reg .pred p;\n\t"
                    "mbarrier.try_wait.parity.acquire.cta.shared::cta.b64 p, [%1], %2;\n\t"
                    "selp.b32 %0, 1, 0, p;\n\t}"
                    : "=r"(done) : "r"(mb[b]), "r"((uint32_t)ph) : "memory");
            } while (!done);
            if (b) ph1 ^= 1; else ph0 ^= 1;

            int rows_this = nrows - (si << 5); if (rows_this > 32) rows_this = 32;
            const float4* B = buf[b];
            if (rows_this == 32) {
                float4 v0 = B[(rl)      * 32 + c];
                float4 v1 = B[(rl + 8)  * 32 + c];
                float4 v2 = B[(rl + 16) * 32 + c];
                float4 v3 = B[(rl + 24) * 32 + c];
                f4add(a0, v0); f4add(a1, v1); f4add(a0, v2); f4add(a1, v3);
            } else {
                #pragma unroll
                for (int k = 0; k < 4; ++k) {
                    int r = rl + 8 * k;
                    if (r < rows_this) f4add(a0, B[r * 32 + c]);
                }
            }
            __syncthreads();
            if (tid == 0 && si + 2 < nst) ISSUE_STAGE(start, nrows, si + 2);
        }

        // tree reduce 8 lanes -> xv = pool + vn_h[m]
        f4add(a0, a1);
        sred[rl][c] = a0;
        __syncthreads();
        if (rl < 4) { f4add(a0, sred[rl + 4][c]); sred[rl][c] = a0; }
        __syncthreads();
        if (rl < 2) { f4add(a0, sred[rl + 2][c]); sred[rl][c] = a0; }
        __syncthreads();
        if (rl == 0) {
            f4add(a0, sred[1][c]);
            float4 vh = *reinterpret_cast<const float4*>(vn_h + (size_t)m * DD + 4 * c);
            f4add(a0, vh);
            *reinterpret_cast<float4*>(&xv[4 * c]) = a0;
        }
        __syncthreads();

        // ---- (b) GEMV epilogue: 2 threads per output row j ----
        {
            const int j    = tid >> 1;
            const int half = tid & 1;
            const float4* Wr = reinterpret_cast<const float4*>(W + (size_t)j * DD + half * 64);
            const float* xp0 = &xv[half * 64];
            float s = 0.f;
            #pragma unroll
            for (int k4 = 0; k4 < 16; ++k4) {
                float4 w = Wr[k4];
                const float* xp = xp0 + k4 * 4;
                s += xp[0] * w.x + xp[1] * w.y + xp[2] * w.z + xp[3] * w.w;
            }
            if (half) part[j] = s;
            __syncthreads();
            if (!half) {
                float t = s + part[j] + bias[j];
                t = t > 0.f ? t : 0.f;
                float y = vn_h[(size_t)m * DD + j] + t;
                yv[j] = y;
                vn_out[(size_t)m * DD + j] = y;
            }
        }

        // ---- steal next segment, prefetch its first stages ----
        if (tid == 0) sm_next = (int)atomicAdd(&g_counter, 1u);
        __syncthreads();   // yv + sm_next visible to all
        const int m2 = sm_next;
        int start2 = 0, end2 = 0, nrows2 = 0, nst2 = 0;
        if (m2 < MG) {
            start2 = g_start[m2]; end2 = g_start[m2 + 1];
            nrows2 = end2 - start2; nst2 = (nrows2 + 31) >> 5;
            if (tid == 0 && nst2 > 0) {
                ISSUE_STAGE(start2, nrows2, 0);
                if (nst2 > 1) ISSUE_STAGE(start2, nrows2, 1);
            }
        }

        // ---- (c) broadcast phase: out_h[row] = h[row] + y (L2 re-read) ----
        {
            const float4 y4 = *reinterpret_cast<const float4*>(&yv[4 * c]);
            int row = start + rl;
            for (; row + 24 < end; row += 32) {
                float4 v0 = __ldcs(h4 + (size_t)(row)      * 32 + c);
                float4 v1 = __ldcs(h4 + (size_t)(row + 8)  * 32 + c);
                float4 v2 = __ldcs(h4 + (size_t)(row + 16) * 32 + c);
                float4 v3 = __ldcs(h4 + (size_t)(row + 24) * 32 + c);
                f4add(v0, y4); f4add(v1, y4); f4add(v2, y4); f4add(v3, y4);
                __stcs(out4 + (size_t)(row)      * 32 + c, v0);
                __stcs(out4 + (size_t)(row + 8)  * 32 + c, v1);
                __stcs(out4 + (size_t)(row + 16) * 32 + c, v2);
                __stcs(out4 + (size_t)(row + 24) * 32 + c, v3);
            }
            for (; row < end; row += 8) {
                float4 v = __ldcs(h4 + (size_t)row * 32 + c);
                f4add(v, y4);
                __stcs(out4 + (size_t)row * 32 + c, v);
            }
        }

        // advance
        m = m2; start = start2; end = end2; nrows = nrows2; nst = nst2;
        __syncthreads();   // protect smem (sred/xv/part/yv) before next segment
    }
    #undef ISSUE_STAGE
}

extern "C" void kernel_launch(void* const* d_in, const int* in_sizes, int n_in,
                              void* d_out, int out_size) {
    const float* h    = (const float*)d_in[0];      // [N, 128]
    const float* vn_h = (const float*)d_in[1];      // [4096, 128]
    const int*   seg  = (const int*)d_in[2];        // [N] sorted int32
    const float* W    = (const float*)d_in[3];      // [128, 128]
    const float* b    = (const float*)d_in[4];      // [128]

    const int N = in_sizes[0] / DD;                   // 1,000,000
    float* out_h  = (float*)d_out;                    // h_new [N,128]
    float* out_vn = (float*)d_out + (size_t)N * DD;   // vn_h_new [4096,128]

    // K0: segment start table + counter reset
    int k0_threads = (N + 3) / 4;
    k0_starts<<<(k0_threads + 255) / 256, 256>>>(seg, N);

    // Fused sum + vn-update + broadcast (persistent work-stealing)
    k_fused<<<K1_BLOCKS, 256>>>(h, vn_h, W, b, out_vn, out_h);
}